// round 1
// baseline (speedup 1.0000x reference)
#include <cuda_runtime.h>

// Problem constants (fixed by the dataset)
#define Bn 16
#define Cn 128
#define Hn 64
#define Wn 64
#define Kn 16
#define Pdeg 3

// knot spacing h = 2/13 ; piece count = 13 ; sentinel pieces at ends -> 15
#define NPIECE 15
#define HF     (2.0f / 13.0f)
#define S3F    ((float)(2.0 / 39.0))   // h/3
#define S23F   ((float)(4.0 / 39.0))   // 2h/3

// Per-channel, per-piece Newton-form cubic coefficients (d0,d1,d2,d3).
// d0 includes bias. Pieces: index 0 = t < -1 sentinel, 1..13 = spans 0..12,
// 14 = t > 1 sentinel.
__device__ float4 g_coef[Cn * NPIECE];

// ---------------------------------------------------------------------------
// Pre-kernel: exact piecewise-cubic extraction in double precision.
// grid = Cn blocks, block = 32 threads (15 active).
// ---------------------------------------------------------------------------
__device__ __forceinline__ double kn_d(int i) {
    if (i <= 3)  return -1.0;
    if (i >= 16) return  1.0;
    return -1.0 + (double)(i - 3) * (2.0 / 13.0);
}

__global__ void precompute_coeffs(const float* __restrict__ alpha,
                                  const float* __restrict__ bias) {
    int c = blockIdx.x;
    int t = threadIdx.x;
    if (t >= NPIECE) return;
    float bv = bias[c];
    int sr = t - 1;           // piece id: -1 .. 13
    float4 out;
    if (sr < 0 || sr > 12) {
        out = make_float4(bv, 0.0f, 0.0f, 0.0f);   // outside [-1,1]: spline = 0
    } else {
        const int span = sr + 3;
        const double s = (2.0 / 13.0) / 3.0;       // node spacing within piece
        const double t0 = -1.0 + (double)sr * (2.0 / 13.0);
        double y[4];
        #pragma unroll
        for (int n = 0; n < 4; n++) {
            double tt = t0 + (double)n * s;
            // fixed-span de Boor (evaluates the polynomial piece of this span)
            double lft[4], rgt[4], Nb[4];
            Nb[0] = 1.0;
            #pragma unroll
            for (int j = 1; j <= 3; j++) {
                lft[j] = tt - kn_d(span + 1 - j);
                rgt[j] = kn_d(span + j) - tt;
                double saved = 0.0;
                #pragma unroll
                for (int r = 0; r < 3; r++) {
                    if (r < j) {
                        double den = rgt[r + 1] + lft[j - r];
                        double tmp = Nb[r] / den;
                        Nb[r] = saved + rgt[r + 1] * tmp;
                        saved = lft[j - r] * tmp;
                    }
                }
                Nb[j] = saved;
            }
            double acc = 0.0;
            #pragma unroll
            for (int j = 0; j < 4; j++)
                acc += Nb[j] * (double)alpha[c * Kn + (span - 3 + j)];
            y[n] = acc;
        }
        // Newton forward divided differences, nodes 0, s, 2s, 3s
        double d0 = y[0];
        double d1 = (y[1] - y[0]) / s;
        double d2 = (y[2] - 2.0 * y[1] + y[0]) / (2.0 * s * s);
        double d3 = (y[3] - 3.0 * y[2] + 3.0 * y[1] - y[0]) / (6.0 * s * s * s);
        out = make_float4((float)(d0 + (double)bv), (float)d1, (float)d2, (float)d3);
    }
    g_coef[c * NPIECE + t] = out;
}

// ---------------------------------------------------------------------------
// Main kernel: one float4 per thread, one channel per block.
// grid = (B*C*H*W/4)/256 = 8192 blocks, block = 256 threads.
// Each (b,c) plane is H*W = 4096 elems = 1024 float4 = 4 blocks.
// ---------------------------------------------------------------------------
__device__ __forceinline__ float eval_one(float x, float av, float bv, float gv,
                                          const float4* sc) {
    float t = fminf(fmaxf(fmaf(x, av, bv), -1.5f), 1.5f);
    float uf  = fmaf(t, 6.5f, 6.5f);       // (t+1) * 13/2
    float srf = floorf(uf);
    int k = (int)srf + 1;
    k = min(k, 13);
    k = max(k, 0);
    if (t > 1.0f) k = 14;                  // strict: t==1 stays in piece 12
    float srcl = fminf(fmaxf(srf, 0.0f), 12.0f);
    float u = t - fmaf(srcl, HF, -1.0f);   // local coordinate within piece
    float4 d = sc[k];
    float p = fmaf(d.w, u - S23F, d.z);
    p = fmaf(p, u - S3F, d.y);
    p = fmaf(p, u, d.x);                   // d.x already includes bias
    return fmaf(gv, x, p);
}

__global__ void __launch_bounds__(256)
kan_spline_main(const float4* __restrict__ x,
                const float*  __restrict__ a,
                const float*  __restrict__ b,
                const float*  __restrict__ gain,
                float4* __restrict__ out) {
    __shared__ float4 sc[NPIECE];
    int bid = blockIdx.x;
    int c = (bid >> 2) & (Cn - 1);         // 4 blocks per (b,c) plane
    if (threadIdx.x < NPIECE)
        sc[threadIdx.x] = g_coef[c * NPIECE + threadIdx.x];
    float av = __ldg(a + c);
    float bv = __ldg(b + c);
    float gv = __ldg(gain + c);
    __syncthreads();

    int i = bid * 256 + threadIdx.x;
    float4 xv = __ldg(x + i);
    float4 ov;
    ov.x = eval_one(xv.x, av, bv, gv, sc);
    ov.y = eval_one(xv.y, av, bv, gv, sc);
    ov.z = eval_one(xv.z, av, bv, gv, sc);
    ov.w = eval_one(xv.w, av, bv, gv, sc);
    out[i] = ov;
}

// ---------------------------------------------------------------------------
// Launch: d_in order = x, a, b, alpha, id_gain, bias
// ---------------------------------------------------------------------------
extern "C" void kernel_launch(void* const* d_in, const int* in_sizes, int n_in,
                              void* d_out, int out_size) {
    const float* x      = (const float*)d_in[0];
    const float* a      = (const float*)d_in[1];
    const float* b      = (const float*)d_in[2];
    const float* alpha  = (const float*)d_in[3];
    const float* gain   = (const float*)d_in[4];
    const float* bias   = (const float*)d_in[5];
    float* out = (float*)d_out;

    precompute_coeffs<<<Cn, 32>>>(alpha, bias);

    const int total4 = (Bn * Cn * Hn * Wn) / 4;   // 2,097,152
    const int blocks = total4 / 256;              // 8192
    kan_spline_main<<<blocks, 256>>>((const float4*)x, a, b, gain, (float4*)out);
}

// round 2
// speedup vs baseline: 1.4556x; 1.4556x over previous
#include <cuda_runtime.h>

// Problem constants (fixed by the dataset)
#define Bn 16
#define Cn 128
#define Hn 64
#define Wn 64
#define Kn 16

// knot spacing h = 2/13 ; 13 real pieces + 2 sentinels = 15 table entries
#define NPIECE 15
#define HF     (2.0f / 13.0f)
#define SF     (2.0f / 39.0f)          // node spacing s = h/3
#define S2F    (4.0f / 39.0f)          // 2s
// exact-in-float divided-difference reciprocals:
#define INV_S    19.5f                 // 1/s
#define INV_2S2  190.125f              // 1/(2 s^2)
#define INV_6S3  1235.8125f            // 1/(6 s^3)

// knot value (degree-3 open-uniform, K=16): indices 0..19
__device__ __forceinline__ float kn_f(int i) {
    i = max(3, min(i, 16));
    return fmaf((float)(i - 3), HF, -1.0f);
}

// Evaluate the spline's polynomial piece `sr` (0..12) at parameter tt,
// using fixed-span de Boor in fp32 with the channel's 4 relevant alphas.
__device__ __forceinline__ float piece_eval(float tt, int sr, const float* al) {
    const int span = sr + 3;
    float lft[4], rgt[4], Nb[4];
    Nb[0] = 1.0f;
    #pragma unroll
    for (int j = 1; j <= 3; j++) {
        lft[j] = tt - kn_f(span + 1 - j);
        rgt[j] = kn_f(span + j) - tt;
        float saved = 0.0f;
        #pragma unroll
        for (int r = 0; r < 3; r++) {
            if (r < j) {
                float den = rgt[r + 1] + lft[j - r];
                float tmp = Nb[r] / den;
                Nb[r] = fmaf(rgt[r + 1], tmp, saved);
                saved = lft[j - r] * tmp;
            }
        }
        Nb[j] = saved;
    }
    return Nb[0] * al[0] + Nb[1] * al[1] + Nb[2] * al[2] + Nb[3] * al[3];
}

// ---------------------------------------------------------------------------
// Fused kernel: table build (threads 0..14) + elementwise map.
// grid = 4096 blocks (2 per (b,c) plane), block = 256, 2 float4 per thread.
// ---------------------------------------------------------------------------
__device__ __forceinline__ float eval_one(float x, float av, float bv, float gv,
                                          const float* s0, const float* s1,
                                          const float* s2, const float* s3) {
    float t = fminf(fmaxf(fmaf(x, av, bv), -1.5f), 1.5f);
    float uf  = fmaf(t, 6.5f, 6.5f);            // (t+1) * 13/2
    float srf = floorf(uf);
    int k = (int)srf + 1;
    k = min(k, 13);
    k = max(k, 0);
    if (t > 1.0f) k = 14;                        // t==1 stays in piece 12
    float srcl = fminf(fmaxf(srf, 0.0f), 12.0f);
    float u = t - fmaf(srcl, HF, -1.0f);         // local coordinate
    float p = fmaf(s3[k], u - S2F, s2[k]);
    p = fmaf(p, u - SF, s1[k]);
    p = fmaf(p, u, s0[k]);                       // s0 includes bias
    return fmaf(gv, x, p);
}

__global__ void __launch_bounds__(256)
kan_spline_fused(const float4* __restrict__ x,
                 const float*  __restrict__ a,
                 const float*  __restrict__ b,
                 const float*  __restrict__ alpha,
                 const float*  __restrict__ gain,
                 const float*  __restrict__ bias,
                 float4* __restrict__ out) {
    // SoA table, 16-entry stride so lane bank == piece index (conflict-free;
    // identical indices broadcast).
    __shared__ float s0[16], s1[16], s2[16], s3[16];

    int bid = blockIdx.x;
    int c = (bid >> 1) & (Cn - 1);               // 2 blocks per (b,c) plane
    int tid = threadIdx.x;

    if (tid < NPIECE) {
        float bv = bias[c];
        int sr = tid - 1;                        // -1 .. 13
        float d0 = bv, d1 = 0.0f, d2 = 0.0f, d3 = 0.0f;
        if (sr >= 0 && sr <= 12) {
            float al[4];
            #pragma unroll
            for (int j = 0; j < 4; j++) al[j] = alpha[c * Kn + sr + j];
            float t0 = fmaf((float)sr, HF, -1.0f);
            float y0 = piece_eval(t0, sr, al);
            float y1 = piece_eval(t0 + SF, sr, al);
            float y2 = piece_eval(t0 + 2.0f * SF, sr, al);
            float y3 = piece_eval(t0 + 3.0f * SF, sr, al);
            d0 = y0 + bv;
            d1 = (y1 - y0) * INV_S;
            d2 = (y2 - 2.0f * y1 + y0) * INV_2S2;
            d3 = (y3 - 3.0f * y2 + 3.0f * y1 - y0) * INV_6S3;
        }
        s0[tid] = d0; s1[tid] = d1; s2[tid] = d2; s3[tid] = d3;
    }
    float av = __ldg(a + c);
    float bv = __ldg(b + c);
    float gv = __ldg(gain + c);
    __syncthreads();

    // 2 float4 per thread: block covers 512 consecutive float4
    int base = bid * 512 + tid;
    float4 x0 = __ldg(x + base);
    float4 x1 = __ldg(x + base + 256);

    float4 o0, o1;
    o0.x = eval_one(x0.x, av, bv, gv, s0, s1, s2, s3);
    o0.y = eval_one(x0.y, av, bv, gv, s0, s1, s2, s3);
    o0.z = eval_one(x0.z, av, bv, gv, s0, s1, s2, s3);
    o0.w = eval_one(x0.w, av, bv, gv, s0, s1, s2, s3);
    o1.x = eval_one(x1.x, av, bv, gv, s0, s1, s2, s3);
    o1.y = eval_one(x1.y, av, bv, gv, s0, s1, s2, s3);
    o1.z = eval_one(x1.z, av, bv, gv, s0, s1, s2, s3);
    o1.w = eval_one(x1.w, av, bv, gv, s0, s1, s2, s3);

    out[base]       = o0;
    out[base + 256] = o1;
}

// ---------------------------------------------------------------------------
// Launch: d_in order = x, a, b, alpha, id_gain, bias
// ---------------------------------------------------------------------------
extern "C" void kernel_launch(void* const* d_in, const int* in_sizes, int n_in,
                              void* d_out, int out_size) {
    const float* x      = (const float*)d_in[0];
    const float* a      = (const float*)d_in[1];
    const float* b      = (const float*)d_in[2];
    const float* alpha  = (const float*)d_in[3];
    const float* gain   = (const float*)d_in[4];
    const float* bias   = (const float*)d_in[5];
    float* out = (float*)d_out;

    const int total4 = (Bn * Cn * Hn * Wn) / 4;   // 2,097,152 float4
    const int blocks = total4 / 512;              // 4096
    kan_spline_fused<<<blocks, 256>>>((const float4*)x, a, b, alpha, gain, bias,
                                      (float4*)out);
}

// round 3
// speedup vs baseline: 1.9589x; 1.3458x over previous
#include <cuda_runtime.h>

// Problem constants (fixed by the dataset)
#define Bn 16
#define Cn 128
#define Hn 64
#define Wn 64
#define Kn 16

#define NPIECE 15
#define HF     (2.0f / 13.0f)
#define SF     (2.0f / 39.0f)          // node spacing s = h/3
#define S2F    (4.0f / 39.0f)          // 2s

// ---------------------------------------------------------------------------
// Compile-time: per-piece 4x4 matrices mapping (al0..al3) -> Newton coeffs.
// All arithmetic in constexpr double; zero runtime divisions.
// ---------------------------------------------------------------------------
constexpr double kn_c(int i) {
    return i <= 3 ? -1.0 : (i >= 16 ? 1.0 : -1.0 + (double)(i - 3) * (2.0 / 13.0));
}

struct B4 { double n[4]; };

constexpr B4 basis_at(double tt, int sr) {
    const int span = sr + 3;
    double lft[4] = {0, 0, 0, 0}, rgt[4] = {0, 0, 0, 0}, Nb[4] = {1.0, 0, 0, 0};
    for (int j = 1; j <= 3; j++) {
        lft[j] = tt - kn_c(span + 1 - j);
        rgt[j] = kn_c(span + j) - tt;
        double saved = 0.0;
        for (int r = 0; r < j; r++) {
            double den = rgt[r + 1] + lft[j - r];
            double tmp = Nb[r] / den;
            Nb[r] = saved + rgt[r + 1] * tmp;
            saved = lft[j - r] * tmp;
        }
        Nb[j] = saved;
    }
    B4 b = {{Nb[0], Nb[1], Nb[2], Nb[3]}};
    return b;
}

struct Tab { float t[13][4][4]; };   // [piece][coeff row][alpha j]

constexpr Tab make_tab() {
    Tab T = {};
    const double s = (2.0 / 13.0) / 3.0;
    for (int sr = 0; sr < 13; sr++) {
        double t0 = -1.0 + (double)sr * (2.0 / 13.0);
        double w[4][4] = {};
        for (int n = 0; n < 4; n++) {
            B4 b = basis_at(t0 + (double)n * s, sr);
            for (int j = 0; j < 4; j++) w[n][j] = b.n[j];
        }
        for (int j = 0; j < 4; j++) {
            T.t[sr][0][j] = (float)(w[0][j]);
            T.t[sr][1][j] = (float)((w[1][j] - w[0][j]) / s);
            T.t[sr][2][j] = (float)((w[2][j] - 2.0 * w[1][j] + w[0][j]) / (2.0 * s * s));
            T.t[sr][3][j] = (float)((w[3][j] - 3.0 * w[2][j] + 3.0 * w[1][j] - w[0][j])
                                    / (6.0 * s * s * s));
        }
    }
    return T;
}

__constant__ Tab c_tab = make_tab();

// ---------------------------------------------------------------------------
// Fused kernel: cheap table build (16 FMA) + elementwise map.
// grid = 2048 blocks (1 per (b,c) plane), block = 256, 4 float4 per thread.
// ---------------------------------------------------------------------------
__device__ __forceinline__ float eval_one(float x, float av, float bv, float gv,
                                          const float* s0, const float* s1,
                                          const float* s2, const float* s3) {
    float t = fminf(fmaxf(fmaf(x, av, bv), -1.5f), 1.5f);
    float uf  = fmaf(t, 6.5f, 6.5f);             // (t+1) * 13/2
    float srf = floorf(uf);
    int k = (int)srf + 1;
    k = min(k, 13);
    k = max(k, 0);
    if (t > 1.0f) k = 14;                        // t==1 stays in piece 12
    // u only matters inside pieces 1..13 (sentinels have d1=d2=d3=0)
    float u = t - fmaf(srf, HF, -1.0f);
    float p = fmaf(s3[k], u - S2F, s2[k]);
    p = fmaf(p, u - SF, s1[k]);
    p = fmaf(p, u, s0[k]);                       // s0 includes bias
    return fmaf(gv, x, p);
}

__global__ void __launch_bounds__(256)
kan_spline_fused(const float4* __restrict__ x,
                 const float*  __restrict__ a,
                 const float*  __restrict__ b,
                 const float*  __restrict__ alpha,
                 const float*  __restrict__ gain,
                 const float*  __restrict__ bias,
                 float4* __restrict__ out) {
    // SoA table: lane bank == piece index -> conflict-free (broadcast on equal k)
    __shared__ float s0[16], s1[16], s2[16], s3[16];

    int bid = blockIdx.x;
    int c = bid & (Cn - 1);                      // plane index = b*128 + c
    int tid = threadIdx.x;

    if (tid < NPIECE) {
        float bv = bias[c];
        int sr = tid - 1;                        // -1 .. 13
        float d0 = bv, d1 = 0.0f, d2 = 0.0f, d3 = 0.0f;
        if (sr >= 0 && sr <= 12) {
            float al0 = alpha[c * Kn + sr];
            float al1 = alpha[c * Kn + sr + 1];
            float al2 = alpha[c * Kn + sr + 2];
            float al3 = alpha[c * Kn + sr + 3];
            const float (*T)[4] = c_tab.t[sr];
            d0 = fmaf(T[0][0], al0, fmaf(T[0][1], al1, fmaf(T[0][2], al2, fmaf(T[0][3], al3, bv))));
            d1 = fmaf(T[1][0], al0, fmaf(T[1][1], al1, fmaf(T[1][2], al2, T[1][3] * al3)));
            d2 = fmaf(T[2][0], al0, fmaf(T[2][1], al1, fmaf(T[2][2], al2, T[2][3] * al3)));
            d3 = fmaf(T[3][0], al0, fmaf(T[3][1], al1, fmaf(T[3][2], al2, T[3][3] * al3)));
        }
        s0[tid] = d0; s1[tid] = d1; s2[tid] = d2; s3[tid] = d3;
    }
    float av = __ldg(a + c);
    float bv2 = __ldg(b + c);
    float gv = __ldg(gain + c);
    __syncthreads();

    // 4 float4 per thread: block covers one 1024-float4 plane
    int base = bid * 1024 + tid;
    float4 x0 = __ldg(x + base);
    float4 x1 = __ldg(x + base + 256);
    float4 x2 = __ldg(x + base + 512);
    float4 x3 = __ldg(x + base + 768);

    float4 o0, o1, o2, o3;
    o0.x = eval_one(x0.x, av, bv2, gv, s0, s1, s2, s3);
    o0.y = eval_one(x0.y, av, bv2, gv, s0, s1, s2, s3);
    o0.z = eval_one(x0.z, av, bv2, gv, s0, s1, s2, s3);
    o0.w = eval_one(x0.w, av, bv2, gv, s0, s1, s2, s3);
    o1.x = eval_one(x1.x, av, bv2, gv, s0, s1, s2, s3);
    o1.y = eval_one(x1.y, av, bv2, gv, s0, s1, s2, s3);
    o1.z = eval_one(x1.z, av, bv2, gv, s0, s1, s2, s3);
    o1.w = eval_one(x1.w, av, bv2, gv, s0, s1, s2, s3);
    o2.x = eval_one(x2.x, av, bv2, gv, s0, s1, s2, s3);
    o2.y = eval_one(x2.y, av, bv2, gv, s0, s1, s2, s3);
    o2.z = eval_one(x2.z, av, bv2, gv, s0, s1, s2, s3);
    o2.w = eval_one(x2.w, av, bv2, gv, s0, s1, s2, s3);
    o3.x = eval_one(x3.x, av, bv2, gv, s0, s1, s2, s3);
    o3.y = eval_one(x3.y, av, bv2, gv, s0, s1, s2, s3);
    o3.z = eval_one(x3.z, av, bv2, gv, s0, s1, s2, s3);
    o3.w = eval_one(x3.w, av, bv2, gv, s0, s1, s2, s3);

    out[base]       = o0;
    out[base + 256] = o1;
    out[base + 512] = o2;
    out[base + 768] = o3;
}

// ---------------------------------------------------------------------------
// Launch: d_in order = x, a, b, alpha, id_gain, bias
// ---------------------------------------------------------------------------
extern "C" void kernel_launch(void* const* d_in, const int* in_sizes, int n_in,
                              void* d_out, int out_size) {
    const float* x      = (const float*)d_in[0];
    const float* a      = (const float*)d_in[1];
    const float* b      = (const float*)d_in[2];
    const float* alpha  = (const float*)d_in[3];
    const float* gain   = (const float*)d_in[4];
    const float* bias   = (const float*)d_in[5];
    float* out = (float*)d_out;

    const int blocks = Bn * Cn;                   // 2048 planes
    kan_spline_fused<<<blocks, 256>>>((const float4*)x, a, b, alpha, gain, bias,
                                      (float4*)out);
}